// round 1
// baseline (speedup 1.0000x reference)
#include <cuda_runtime.h>

// Problem constants
#define BB    256
#define HS    128
#define KITER 40

// Padded shared tile: rows -1..128 -> 130, cols -1..130 -> stride 132
#define S  132
#define PR 130

#define SMEM_FLOATS (3*PR*S + 90 + 90 + 16)
#define SMEM_BYTES  (SMEM_FLOATS * 4)

__device__ float g_eff[19];   // collapsed h->r weights (18) + bias (1)

// ---------------- prep: collapse h_w/h_b/r_w into 2x3x3 eff conv ----------------
__global__ void vin_prep(const float* __restrict__ h_w,
                         const float* __restrict__ h_b,
                         const float* __restrict__ r_w) {
    int t = threadIdx.x;
    if (t < 18) {
        float s = 0.f;
        for (int c = 0; c < 150; ++c) s += r_w[c] * h_w[c*18 + t];
        g_eff[t] = s;
    } else if (t == 18) {
        float s = 0.f;
        for (int c = 0; c < 150; ++c) s += r_w[c] * h_b[c];
        g_eff[18] = s;
    }
}

// ---------------- f32x2 helpers ----------------
__device__ __forceinline__ unsigned long long dup2(float x) {
    unsigned long long d;
    asm("mov.b64 %0, {%1, %1};" : "=l"(d) : "f"(x));
    return d;
}
__device__ __forceinline__ unsigned long long fma2(unsigned long long a,
                                                   unsigned long long b,
                                                   unsigned long long c) {
    unsigned long long d;
    asm("fma.rn.f32x2 %0, %1, %2, %3;" : "=l"(d) : "l"(a), "l"(b), "l"(c));
    return d;
}
__device__ __forceinline__ unsigned long long mul2(unsigned long long a,
                                                   unsigned long long b) {
    unsigned long long d;
    asm("mul.rn.f32x2 %0, %1, %2;" : "=l"(d) : "l"(a), "l"(b));
    return d;
}
__device__ __forceinline__ float2 u2f(unsigned long long u) {
    float2 f;
    asm("mov.b64 {%0, %1}, %2;" : "=f"(f.x), "=f"(f.y) : "l"(u));
    return f;
}

extern __shared__ float smem[];

// ---------------- main: one CTA per batch image, persistent VI loop ----------------
__global__ __launch_bounds__(256, 1)
void vin_main(const float* __restrict__ input_view,
              const int*   __restrict__ coords,
              const float* __restrict__ q_w,
              const float* __restrict__ w,
              const float* __restrict__ fc_w,
              float*       __restrict__ out) {
    const int b   = blockIdx.x;
    const int tid = threadIdx.x;

    float* r_s  = smem;                 // [PR][S], zero halo
    float* v0   = smem + PR*S;
    float* v1   = smem + 2*PR*S;
    float* wr_s = smem + 3*PR*S;        // 45 packed channel-pairs * 9 taps * 2 (r weights = q_w)
    float* wv_s = wr_s + 90;            // same for v weights = w
    float* qfin = wv_s + 90;            // 10 final q values at coord

    // zero everything (borders + initial v = 0)
    for (int i = tid; i < 3*PR*S; i += 256) smem[i] = 0.f;

    // pack weights as channel-pairs: wr_s[(cp*9+t)*2 + (c&1)]
    if (tid < 90) {
        int c = tid / 9, t = tid % 9;
        int cp = c >> 1, half = c & 1;
        wr_s[(cp*9 + t)*2 + half] = q_w[c*9 + t];
        wv_s[(cp*9 + t)*2 + half] = w[c*9 + t];
    }
    __syncthreads();

    // ---- compute r tile (collapsed front-end conv, pad=1) ----
    {
        float e[19];
        #pragma unroll
        for (int i = 0; i < 19; ++i) e[i] = g_eff[i];
        const float* inb = input_view + (size_t)b * 2 * HS * HS;
        for (int idx = tid; idx < HS*HS; idx += 256) {
            int y = idx >> 7, x = idx & 127;
            float acc = e[18];
            #pragma unroll
            for (int ch = 0; ch < 2; ++ch) {
                const float* ip = inb + ch * HS * HS;
                #pragma unroll
                for (int ky = 0; ky < 3; ++ky) {
                    int yy = y + ky - 1;
                    if ((unsigned)yy < (unsigned)HS) {
                        #pragma unroll
                        for (int kx = 0; kx < 3; ++kx) {
                            int xx = x + kx - 1;
                            if ((unsigned)xx < (unsigned)HS)
                                acc += ip[yy*HS + xx] * e[ch*9 + ky*3 + kx];
                        }
                    }
                }
            }
            r_s[(y+1)*S + x + 1] = acc;
        }
    }
    __syncthreads();

    // ---- 40 value-iteration sweeps ----
    #pragma unroll 1
    for (int it = 0; it < KITER; ++it) {
        const float* vc = (it & 1) ? v1 : v0;
        float*       vn = (it & 1) ? v0 : v1;

        #pragma unroll 1
        for (int k = 0; k < 8; ++k) {
            int seg = tid + (k << 8);          // 2048 segments of 8 pixels
            int y   = seg >> 4;                // 0..127
            int x0  = (seg & 15) << 3;         // 0..120

            // load patches (padded rows y..y+2, padded cols x0..x0+9), dup to f32x2
            unsigned long long rd[3][10], vd[3][10];
            #pragma unroll
            for (int rr = 0; rr < 3; ++rr) {
                const float* rrow = r_s + (y + rr)*S + x0;
                const float* vrow = vc  + (y + rr)*S + x0;
                #pragma unroll
                for (int cc = 0; cc < 10; ++cc) {
                    rd[rr][cc] = dup2(rrow[cc]);
                    vd[rr][cc] = dup2(vrow[cc]);
                }
            }

            float vmx[8], vmy[8];
            #pragma unroll
            for (int cp = 0; cp < 5; ++cp) {
                unsigned long long WR[9], WV[9];
                #pragma unroll
                for (int t = 0; t < 9; ++t) {
                    WR[t] = *(const unsigned long long*)(wr_s + (cp*9 + t)*2);
                    WV[t] = *(const unsigned long long*)(wv_s + (cp*9 + t)*2);
                }
                #pragma unroll
                for (int px = 0; px < 8; ++px) {
                    unsigned long long acc = mul2(rd[0][px], WR[0]);
                    acc = fma2(rd[0][px+1], WR[1], acc);
                    acc = fma2(rd[0][px+2], WR[2], acc);
                    acc = fma2(rd[1][px],   WR[3], acc);
                    acc = fma2(rd[1][px+1], WR[4], acc);
                    acc = fma2(rd[1][px+2], WR[5], acc);
                    acc = fma2(rd[2][px],   WR[6], acc);
                    acc = fma2(rd[2][px+1], WR[7], acc);
                    acc = fma2(rd[2][px+2], WR[8], acc);
                    acc = fma2(vd[0][px],   WV[0], acc);
                    acc = fma2(vd[0][px+1], WV[1], acc);
                    acc = fma2(vd[0][px+2], WV[2], acc);
                    acc = fma2(vd[1][px],   WV[3], acc);
                    acc = fma2(vd[1][px+1], WV[4], acc);
                    acc = fma2(vd[1][px+2], WV[5], acc);
                    acc = fma2(vd[2][px],   WV[6], acc);
                    acc = fma2(vd[2][px+1], WV[7], acc);
                    acc = fma2(vd[2][px+2], WV[8], acc);
                    float2 a = u2f(acc);
                    if (cp == 0) { vmx[px] = a.x;                vmy[px] = a.y; }
                    else         { vmx[px] = fmaxf(vmx[px], a.x); vmy[px] = fmaxf(vmy[px], a.y); }
                }
            }

            float* vout = vn + (y+1)*S + x0 + 1;
            #pragma unroll
            for (int px = 0; px < 8; ++px)
                vout[px] = fmaxf(vmx[px], vmy[px]);
        }
        __syncthreads();
    }

    // ---- final conv at (sx, sy) only + FC ----
    // after 40 iterations (even), final v lives in v0
    const float* vf = v0;
    if (tid < 10) {
        int sx = coords[b*4 + 0];
        int sy = coords[b*4 + 1];
        float acc = 0.f;
        #pragma unroll
        for (int rr = 0; rr < 3; ++rr) {
            #pragma unroll
            for (int cc = 0; cc < 3; ++cc) {
                int t = rr*3 + cc;
                float rp = r_s[(sx + rr)*S + (sy + cc)];
                float vp = vf [(sx + rr)*S + (sy + cc)];
                acc += rp * q_w[tid*9 + t] + vp * w[tid*9 + t];
            }
        }
        qfin[tid] = acc;
    }
    __syncthreads();
    if (tid < 5) {
        float s = 0.f;
        #pragma unroll
        for (int c = 0; c < 10; ++c) s += qfin[c] * fc_w[tid*10 + c];
        out[b*5 + tid] = s;
    }
}

extern "C" void kernel_launch(void* const* d_in, const int* in_sizes, int n_in,
                              void* d_out, int out_size) {
    const float* input_view = (const float*)d_in[0];
    const int*   coords     = (const int*)  d_in[1];
    const float* h_w        = (const float*)d_in[2];
    const float* h_b        = (const float*)d_in[3];
    const float* r_w        = (const float*)d_in[4];
    const float* q_w        = (const float*)d_in[5];
    const float* w          = (const float*)d_in[6];
    const float* fc_w       = (const float*)d_in[7];
    float* out = (float*)d_out;

    (void)in_sizes; (void)n_in; (void)out_size;

    vin_prep<<<1, 32>>>(h_w, h_b, r_w);

    cudaFuncSetAttribute(vin_main, cudaFuncAttributeMaxDynamicSharedMemorySize, SMEM_BYTES);
    vin_main<<<BB, 256, SMEM_BYTES>>>(input_view, coords, q_w, w, fc_w, out);
}

// round 2
// speedup vs baseline: 1.2607x; 1.2607x over previous
#include <cuda_runtime.h>
#include <cstdint>

#define HS    128
#define KITER 40
#define NIMG  256
#define RPC   16            // rows per CTA
#define NCTA  8             // cluster size (8 * 16 = 128 rows)
#define S     132           // padded row stride (floats)
#define VROWS 18            // RPC + 2 halo rows

#define CR_U64     (40*256)           // (8 px * 5 cp) * 256 threads, u64 each
#define VBUF_F     (VROWS*S)          // 2376 floats
#define SM_FLOATS  (CR_U64*2 + 2*VBUF_F + 90 + 90 + 16)
#define SMEM_BYTES (SM_FLOATS*4)

__device__ float g_eff[19];   // collapsed h->r conv weights (18) + bias

// ---------------- prep: collapse h_w/h_b/r_w into 2x3x3 eff conv ----------------
__global__ void vin_prep(const float* __restrict__ h_w,
                         const float* __restrict__ h_b,
                         const float* __restrict__ r_w) {
    int t = threadIdx.x;
    if (t < 18) {
        float s = 0.f;
        for (int c = 0; c < 150; ++c) s += r_w[c] * h_w[c*18 + t];
        g_eff[t] = s;
    } else if (t == 18) {
        float s = 0.f;
        for (int c = 0; c < 150; ++c) s += r_w[c] * h_b[c];
        g_eff[18] = s;
    }
}

// ---------------- f32x2 / PTX helpers ----------------
__device__ __forceinline__ unsigned long long dup2(float x) {
    unsigned long long d;
    asm("mov.b64 %0, {%1, %1};" : "=l"(d) : "f"(x));
    return d;
}
__device__ __forceinline__ unsigned long long fma2(unsigned long long a,
                                                   unsigned long long b,
                                                   unsigned long long c) {
    unsigned long long d;
    asm("fma.rn.f32x2 %0, %1, %2, %3;" : "=l"(d) : "l"(a), "l"(b), "l"(c));
    return d;
}
__device__ __forceinline__ unsigned long long mul2(unsigned long long a,
                                                   unsigned long long b) {
    unsigned long long d;
    asm("mul.rn.f32x2 %0, %1, %2;" : "=l"(d) : "l"(a), "l"(b));
    return d;
}
__device__ __forceinline__ float2 u2f(unsigned long long u) {
    float2 f;
    asm("mov.b64 {%0, %1}, %2;" : "=f"(f.x), "=f"(f.y) : "l"(u));
    return f;
}
__device__ __forceinline__ uint32_t smem_u32(const void* p) {
    uint32_t a;
    asm("{ .reg .u64 t; cvta.to.shared.u64 t, %1; cvt.u32.u64 %0, t; }"
        : "=r"(a) : "l"(p));
    return a;
}
__device__ __forceinline__ float dsmem_ld(const float* p, uint32_t rank) {
    uint32_t a = smem_u32(p), r;
    asm("mapa.shared::cluster.u32 %0, %1, %2;" : "=r"(r) : "r"(a), "r"(rank));
    float v;
    asm volatile("ld.shared::cluster.f32 %0, [%1];" : "=f"(v) : "r"(r));
    return v;
}
#define CLUSTER_ARRIVE() asm volatile("barrier.cluster.arrive.aligned;" ::: "memory")
#define CLUSTER_WAIT()   asm volatile("barrier.cluster.wait.aligned;"   ::: "memory")

extern __shared__ float smem[];

// ---------------- main: 8-CTA cluster per image, 16 rows per CTA ----------------
__global__ void __launch_bounds__(256, 2) __cluster_dims__(NCTA, 1, 1)
vin_main(const float* __restrict__ input_view,
         const int*   __restrict__ coords,
         const float* __restrict__ q_w,
         const float* __restrict__ w,
         const float* __restrict__ fc_w,
         float*       __restrict__ out)
{
    unsigned long long* cr = (unsigned long long*)smem;   // [(px*5+cp)*256 + tid]
    float* buf0 = smem + CR_U64*2;
    float* buf1 = buf0 + VBUF_F;
    float* wq_s = buf1 + VBUF_F;   // q_w packed as channel-pairs
    float* wv_s = wq_s + 90;       // w   packed as channel-pairs
    float* qfin = wv_s + 90;

    const int tid  = threadIdx.x;
    const int img  = blockIdx.x >> 3;
    const int rank = blockIdx.x & 7;
    const int r0   = rank * RPC;

    // zero both v buffers (halos included; buf0 is initial v = 0)
    for (int i = tid; i < 2*VBUF_F; i += 256) buf0[i] = 0.f;
    if (tid < 90) {
        int c = tid/9, t9 = tid%9, cp = c>>1, half = c&1;
        wq_s[(cp*9 + t9)*2 + half] = q_w[c*9 + t9];
        wv_s[(cp*9 + t9)*2 + half] = w  [c*9 + t9];
    }
    __syncthreads();

    // ---- stage A: r rows [r0-1, r0+16] into buf1 (temp), zero outside image ----
    {
        float e[19];
        #pragma unroll
        for (int i = 0; i < 19; ++i) e[i] = g_eff[i];
        const float* inb = input_view + (size_t)img * 2 * HS * HS;
        for (int idx = tid; idx < VROWS*HS; idx += 256) {
            int j = idx >> 7, x = idx & 127;
            int gy = r0 - 1 + j;
            float acc = 0.f;
            if ((unsigned)gy < (unsigned)HS) {
                acc = e[18];
                #pragma unroll
                for (int ch = 0; ch < 2; ++ch) {
                    const float* ip = inb + ch*HS*HS;
                    #pragma unroll
                    for (int ky = 0; ky < 3; ++ky) {
                        int yy = gy + ky - 1;
                        if ((unsigned)yy < (unsigned)HS) {
                            #pragma unroll
                            for (int kx = 0; kx < 3; ++kx) {
                                int xx = x + kx - 1;
                                if ((unsigned)xx < (unsigned)HS)
                                    acc += ip[yy*HS + xx] * e[ch*9 + ky*3 + kx];
                            }
                        }
                    }
                }
            }
            buf1[j*S + x + 1] = acc;
        }
    }
    __syncthreads();

    const int y  = tid >> 4;          // owned row 0..15
    const int x0 = (tid & 15) << 3;   // 0..120

    // ---- stage B: cr[c][px] = conv(r, q_w_c), channel-pair u64, transposed layout ----
    {
        unsigned long long rd[3][10];
        #pragma unroll
        for (int rr = 0; rr < 3; ++rr) {
            const float4* p = (const float4*)(buf1 + (y+rr)*S + x0);
            float4 a = p[0], b4 = p[1], c4 = p[2];
            rd[rr][0]=dup2(a.x);  rd[rr][1]=dup2(a.y);  rd[rr][2]=dup2(a.z);  rd[rr][3]=dup2(a.w);
            rd[rr][4]=dup2(b4.x); rd[rr][5]=dup2(b4.y); rd[rr][6]=dup2(b4.z); rd[rr][7]=dup2(b4.w);
            rd[rr][8]=dup2(c4.x); rd[rr][9]=dup2(c4.y);
        }
        #pragma unroll
        for (int cp = 0; cp < 5; ++cp) {
            unsigned long long W[9];
            #pragma unroll
            for (int t9 = 0; t9 < 9; ++t9)
                W[t9] = *(const unsigned long long*)(wq_s + (cp*9 + t9)*2);
            #pragma unroll
            for (int px = 0; px < 8; ++px) {
                unsigned long long acc = mul2(rd[0][px], W[0]);
                acc = fma2(rd[0][px+1], W[1], acc);
                acc = fma2(rd[0][px+2], W[2], acc);
                acc = fma2(rd[1][px],   W[3], acc);
                acc = fma2(rd[1][px+1], W[4], acc);
                acc = fma2(rd[1][px+2], W[5], acc);
                acc = fma2(rd[2][px],   W[6], acc);
                acc = fma2(rd[2][px+1], W[7], acc);
                acc = fma2(rd[2][px+2], W[8], acc);
                cr[(px*5 + cp)*256 + tid] = acc;
            }
        }
    }
    __syncthreads();
    // buf1 becomes a v buffer: re-zero it
    for (int i = tid; i < VBUF_F; i += 256) buf1[i] = 0.f;
    __syncthreads();

    // ---- 40 value-iteration sweeps (v-conv only; cr folded into accumulator init) ----
    #pragma unroll 1
    for (int it = 0; it < KITER; ++it) {
        const float* vc = (it & 1) ? buf1 : buf0;
        float*       vn = (it & 1) ? buf0 : buf1;

        unsigned long long vd[3][10];
        #pragma unroll
        for (int rr = 0; rr < 3; ++rr) {
            const float4* p = (const float4*)(vc + (y+rr)*S + x0);
            float4 a = p[0], b4 = p[1], c4 = p[2];
            vd[rr][0]=dup2(a.x);  vd[rr][1]=dup2(a.y);  vd[rr][2]=dup2(a.z);  vd[rr][3]=dup2(a.w);
            vd[rr][4]=dup2(b4.x); vd[rr][5]=dup2(b4.y); vd[rr][6]=dup2(b4.z); vd[rr][7]=dup2(b4.w);
            vd[rr][8]=dup2(c4.x); vd[rr][9]=dup2(c4.y);
        }

        float vmx[8], vmy[8];
        #pragma unroll
        for (int cp = 0; cp < 5; ++cp) {
            unsigned long long W[9];
            #pragma unroll
            for (int t9 = 0; t9 < 9; ++t9)
                W[t9] = *(const unsigned long long*)(wv_s + (cp*9 + t9)*2);
            #pragma unroll
            for (int px = 0; px < 8; ++px) {
                unsigned long long acc = cr[(px*5 + cp)*256 + tid];
                acc = fma2(vd[0][px],   W[0], acc);
                acc = fma2(vd[0][px+1], W[1], acc);
                acc = fma2(vd[0][px+2], W[2], acc);
                acc = fma2(vd[1][px],   W[3], acc);
                acc = fma2(vd[1][px+1], W[4], acc);
                acc = fma2(vd[1][px+2], W[5], acc);
                acc = fma2(vd[2][px],   W[6], acc);
                acc = fma2(vd[2][px+1], W[7], acc);
                acc = fma2(vd[2][px+2], W[8], acc);
                float2 aa = u2f(acc);
                if (cp == 0) { vmx[px] = aa.x;                 vmy[px] = aa.y; }
                else         { vmx[px] = fmaxf(vmx[px], aa.x); vmy[px] = fmaxf(vmy[px], aa.y); }
            }
        }
        float* vo = vn + (y+1)*S + x0 + 1;
        #pragma unroll
        for (int px = 0; px < 8; ++px) vo[px] = fmaxf(vmx[px], vmy[px]);

        // cluster-wide: everyone finished writing vn; then pull halo rows via DSMEM
        CLUSTER_ARRIVE();
        CLUSTER_WAIT();
        if (tid < 128) {
            if (rank > 0)
                vn[0*S + 1 + tid] = dsmem_ld(vn + 16*S + 1 + tid, rank - 1);
        } else {
            int t2 = tid - 128;
            if (rank < NCTA-1)
                vn[17*S + 1 + t2] = dsmem_ld(vn + 1*S + 1 + t2, rank + 1);
        }
        __syncthreads();
    }

    // ---- readout: final v is buf0 (it=39 wrote buf0) ----
    const int sx = coords[img*4 + 0];
    const int sy = coords[img*4 + 1];
    if ((sx >> 4) == rank) {
        const float* vf = buf0;
        const int yl = sx & 15;
        if (tid < 10) {
            int tt = yl*16 + (sy >> 3), slot = sy & 7;
            int cp = tid >> 1, half = tid & 1;
            float2 crv = u2f(cr[(slot*5 + cp)*256 + tt]);
            float acc = half ? crv.y : crv.x;
            #pragma unroll
            for (int rr = 0; rr < 3; ++rr)
                #pragma unroll
                for (int cc = 0; cc < 3; ++cc)
                    acc += w[tid*9 + rr*3 + cc] * vf[(yl + rr)*S + sy + cc];
            qfin[tid] = acc;
        }
        __syncthreads();
        if (tid < 5) {
            float s = 0.f;
            #pragma unroll
            for (int c = 0; c < 10; ++c) s += qfin[c] * fc_w[tid*10 + c];
            out[img*5 + tid] = s;
        }
    }
}

extern "C" void kernel_launch(void* const* d_in, const int* in_sizes, int n_in,
                              void* d_out, int out_size) {
    const float* input_view = (const float*)d_in[0];
    const int*   coords     = (const int*)  d_in[1];
    const float* h_w        = (const float*)d_in[2];
    const float* h_b        = (const float*)d_in[3];
    const float* r_w        = (const float*)d_in[4];
    const float* q_w        = (const float*)d_in[5];
    const float* w          = (const float*)d_in[6];
    const float* fc_w       = (const float*)d_in[7];
    float* out = (float*)d_out;

    (void)in_sizes; (void)n_in; (void)out_size;

    vin_prep<<<1, 32>>>(h_w, h_b, r_w);

    cudaFuncSetAttribute(vin_main, cudaFuncAttributeMaxDynamicSharedMemorySize, SMEM_BYTES);
    vin_main<<<NIMG*NCTA, 256, SMEM_BYTES>>>(input_view, coords, q_w, w, fc_w, out);
}

// round 6
// speedup vs baseline: 1.2720x; 1.0089x over previous
#include <cuda_runtime.h>
#include <cstdint>

#define HS    128
#define KITER 40
#define NIMG  256
#define RPC   16            // rows per CTA
#define NCTA  8             // cluster size (8 * 16 = 128 rows)
#define S     132           // padded row stride (floats)
#define VROWS 18            // RPC + 2 halo rows
#define NTHR  256

#define CR_U64     (5*8*NTHR)          // 5 ch-pairs * 8 px * 256 threads
#define VBUF_F     (VROWS*S)           // 2376 floats
#define SM_FLOATS  (CR_U64*2 + 2*VBUF_F + 90 + 90 + 16)
#define SMEM_BYTES (SM_FLOATS*4)

__device__ float g_eff[19];   // collapsed h->r conv weights (18) + bias

// ---------------- prep: collapse h_w/h_b/r_w into 2x3x3 eff conv ----------------
__global__ void vin_prep(const float* __restrict__ h_w,
                         const float* __restrict__ h_b,
                         const float* __restrict__ r_w) {
    int t = threadIdx.x;
    if (t < 18) {
        float s = 0.f;
        for (int c = 0; c < 150; ++c) s += r_w[c] * h_w[c*18 + t];
        g_eff[t] = s;
    } else if (t == 18) {
        float s = 0.f;
        for (int c = 0; c < 150; ++c) s += r_w[c] * h_b[c];
        g_eff[18] = s;
    }
}

// ---------------- f32x2 / PTX helpers ----------------
__device__ __forceinline__ unsigned long long dup2(float x) {
    unsigned long long d;
    asm("mov.b64 %0, {%1, %1};" : "=l"(d) : "f"(x));
    return d;
}
__device__ __forceinline__ unsigned long long fma2(unsigned long long a,
                                                   unsigned long long b,
                                                   unsigned long long c) {
    unsigned long long d;
    asm("fma.rn.f32x2 %0, %1, %2, %3;" : "=l"(d) : "l"(a), "l"(b), "l"(c));
    return d;
}
__device__ __forceinline__ unsigned long long mul2(unsigned long long a,
                                                   unsigned long long b) {
    unsigned long long d;
    asm("mul.rn.f32x2 %0, %1, %2;" : "=l"(d) : "l"(a), "l"(b));
    return d;
}
__device__ __forceinline__ float2 u2f(unsigned long long u) {
    float2 f;
    asm("mov.b64 {%0, %1}, %2;" : "=f"(f.x), "=f"(f.y) : "l"(u));
    return f;
}
__device__ __forceinline__ uint32_t smem_u32(const void* p) {
    uint32_t a;
    asm("{ .reg .u64 t; cvta.to.shared.u64 t, %1; cvt.u32.u64 %0, t; }"
        : "=r"(a) : "l"(p));
    return a;
}
__device__ __forceinline__ float dsmem_ld(const float* p, uint32_t rank) {
    uint32_t a = smem_u32(p), r;
    asm("mapa.shared::cluster.u32 %0, %1, %2;" : "=r"(r) : "r"(a), "r"(rank));
    float v;
    asm volatile("ld.shared::cluster.f32 %0, [%1];" : "=f"(v) : "r"(r));
    return v;
}
#define CLUSTER_ARRIVE() asm volatile("barrier.cluster.arrive.aligned;" ::: "memory")
#define CLUSTER_WAIT()   asm volatile("barrier.cluster.wait.aligned;"   ::: "memory")

extern __shared__ float smem[];

// ---------------- main: 8-CTA cluster per image, 16 rows per CTA ----------------
__global__ void __launch_bounds__(NTHR, 2) __cluster_dims__(NCTA, 1, 1)
vin_main(const float* __restrict__ input_view,
         const int*   __restrict__ coords,
         const float* __restrict__ q_w,
         const float* __restrict__ w,
         const float* __restrict__ fc_w,
         float*       __restrict__ out)
{
    unsigned long long* cr = (unsigned long long*)smem;   // [(px*5+cp)*256 + tid]
    float* buf0 = smem + CR_U64*2;
    float* buf1 = buf0 + VBUF_F;
    float* wq_s = buf1 + VBUF_F;   // q_w packed as channel-pairs
    float* wv_s = wq_s + 90;       // w   packed as channel-pairs
    float* qfin = wv_s + 90;

    const int tid  = threadIdx.x;
    const int img  = blockIdx.x >> 3;
    const int rank = blockIdx.x & 7;
    const int r0   = rank * RPC;

    // zero both v buffers (halos included; buf0 is initial v = 0)
    for (int i = tid; i < 2*VBUF_F; i += NTHR) buf0[i] = 0.f;
    if (tid < 90) {
        int c = tid/9, t9 = tid%9, cp = c>>1, half = c&1;
        wq_s[(cp*9 + t9)*2 + half] = q_w[c*9 + t9];
        wv_s[(cp*9 + t9)*2 + half] = w  [c*9 + t9];
    }
    __syncthreads();

    // ---- stage A: r rows [r0-1, r0+16] into buf1 (temp), zero outside image ----
    {
        float e[19];
        #pragma unroll
        for (int i = 0; i < 19; ++i) e[i] = g_eff[i];
        const float* inb = input_view + (size_t)img * 2 * HS * HS;
        for (int idx = tid; idx < VROWS*HS; idx += NTHR) {
            int j = idx >> 7, x = idx & 127;
            int gy = r0 - 1 + j;
            float acc = 0.f;
            if ((unsigned)gy < (unsigned)HS) {
                acc = e[18];
                #pragma unroll
                for (int ch = 0; ch < 2; ++ch) {
                    const float* ip = inb + ch*HS*HS;
                    #pragma unroll
                    for (int ky = 0; ky < 3; ++ky) {
                        int yy = gy + ky - 1;
                        if ((unsigned)yy < (unsigned)HS) {
                            #pragma unroll
                            for (int kx = 0; kx < 3; ++kx) {
                                int xx = x + kx - 1;
                                if ((unsigned)xx < (unsigned)HS)
                                    acc += ip[yy*HS + xx] * e[ch*9 + ky*3 + kx];
                            }
                        }
                    }
                }
            }
            buf1[j*S + x + 1] = acc;
        }
    }
    __syncthreads();

    const int y  = tid >> 4;          // owned row 0..15
    const int x0 = (tid & 15) << 3;   // 0..120

    // ---- stage B: cr[c][px] = conv(r, q_w_c), channel-pair u64, transposed ----
    {
        unsigned long long rd[3][10];
        #pragma unroll
        for (int rr = 0; rr < 3; ++rr) {
            const float4* p = (const float4*)(buf1 + (y+rr)*S + x0);
            float4 a = p[0], b4 = p[1], c4 = p[2];
            rd[rr][0]=dup2(a.x);  rd[rr][1]=dup2(a.y);  rd[rr][2]=dup2(a.z);  rd[rr][3]=dup2(a.w);
            rd[rr][4]=dup2(b4.x); rd[rr][5]=dup2(b4.y); rd[rr][6]=dup2(b4.z); rd[rr][7]=dup2(b4.w);
            rd[rr][8]=dup2(c4.x); rd[rr][9]=dup2(c4.y);
        }
        #pragma unroll
        for (int cp = 0; cp < 5; ++cp) {
            unsigned long long W[9];
            #pragma unroll
            for (int t9 = 0; t9 < 9; ++t9)
                W[t9] = *(const unsigned long long*)(wq_s + (cp*9 + t9)*2);
            #pragma unroll
            for (int px = 0; px < 8; ++px) {
                unsigned long long acc = mul2(rd[0][px], W[0]);
                acc = fma2(rd[0][px+1], W[1], acc);
                acc = fma2(rd[0][px+2], W[2], acc);
                acc = fma2(rd[1][px],   W[3], acc);
                acc = fma2(rd[1][px+1], W[4], acc);
                acc = fma2(rd[1][px+2], W[5], acc);
                acc = fma2(rd[2][px],   W[6], acc);
                acc = fma2(rd[2][px+1], W[7], acc);
                acc = fma2(rd[2][px+2], W[8], acc);
                cr[(px*5 + cp)*NTHR + tid] = acc;
            }
        }
    }
    __syncthreads();
    // buf1 becomes a v buffer: re-zero it
    for (int i = tid; i < VBUF_F; i += NTHR) buf1[i] = 0.f;
    __syncthreads();

    // ---- 40 value-iteration sweeps ----
    #pragma unroll 1
    for (int it = 0; it < KITER; ++it) {
        const float* vc = (it & 1) ? buf1 : buf0;
        float*       vn = (it & 1) ? buf0 : buf1;

        unsigned long long vd[3][10];
        #pragma unroll
        for (int rr = 0; rr < 3; ++rr) {
            const float4* p = (const float4*)(vc + (y+rr)*S + x0);
            float4 a = p[0], b4 = p[1], c4 = p[2];
            vd[rr][0]=dup2(a.x);  vd[rr][1]=dup2(a.y);  vd[rr][2]=dup2(a.z);  vd[rr][3]=dup2(a.w);
            vd[rr][4]=dup2(b4.x); vd[rr][5]=dup2(b4.y); vd[rr][6]=dup2(b4.z); vd[rr][7]=dup2(b4.w);
            vd[rr][8]=dup2(c4.x); vd[rr][9]=dup2(c4.y);
        }

        float vmx[8], vmy[8];
        #pragma unroll
        for (int cp = 0; cp < 5; ++cp) {
            unsigned long long W[9];
            #pragma unroll
            for (int t9 = 0; t9 < 9; ++t9)
                W[t9] = *(const unsigned long long*)(wv_s + (cp*9 + t9)*2);
            #pragma unroll
            for (int px = 0; px < 8; ++px) {
                unsigned long long acc = cr[(px*5 + cp)*NTHR + tid];
                acc = fma2(vd[0][px],   W[0], acc);
                acc = fma2(vd[0][px+1], W[1], acc);
                acc = fma2(vd[0][px+2], W[2], acc);
                acc = fma2(vd[1][px],   W[3], acc);
                acc = fma2(vd[1][px+1], W[4], acc);
                acc = fma2(vd[1][px+2], W[5], acc);
                acc = fma2(vd[2][px],   W[6], acc);
                acc = fma2(vd[2][px+1], W[7], acc);
                acc = fma2(vd[2][px+2], W[8], acc);
                float2 aa = u2f(acc);
                if (cp == 0) { vmx[px] = aa.x;                 vmy[px] = aa.y; }
                else         { vmx[px] = fmaxf(vmx[px], aa.x); vmy[px] = fmaxf(vmy[px], aa.y); }
            }
        }
        float* vo = vn + (y+1)*S + x0 + 1;
        #pragma unroll
        for (int px = 0; px < 8; ++px) vo[px] = fmaxf(vmx[px], vmy[px]);

        // cluster-wide: everyone finished writing vn; then pull halo rows via DSMEM
        CLUSTER_ARRIVE();
        CLUSTER_WAIT();
        // each thread fetches one pixel from each neighbor's boundary row
        if (tid < 128) {
            if (rank > 0)
                vn[0*S + 1 + tid]       = dsmem_ld(vn + RPC*S + 1 + tid, rank - 1);
        } else {
            int t2 = tid - 128;
            if (rank < NCTA-1)
                vn[(RPC+1)*S + 1 + t2]  = dsmem_ld(vn + 1*S + 1 + t2, rank + 1);
        }
        __syncthreads();
    }

    // ---- readout: final v is buf0 (it=39 wrote buf0) ----
    const int sx = coords[img*4 + 0];
    const int sy = coords[img*4 + 1];
    if ((sx >> 4) == rank) {
        const float* vf = buf0;
        const int yl = sx & 15;
        if (tid < 10) {
            int tt = yl*16 + (sy >> 3), slot = sy & 7;
            int cp = tid >> 1, half = tid & 1;
            float2 crv = u2f(cr[(slot*5 + cp)*NTHR + tt]);
            float acc = half ? crv.y : crv.x;
            #pragma unroll
            for (int rr = 0; rr < 3; ++rr)
                #pragma unroll
                for (int cc = 0; cc < 3; ++cc)
                    acc += w[tid*9 + rr*3 + cc] * vf[(yl + rr)*S + sy + cc];
            qfin[tid] = acc;
        }
        __syncthreads();
        if (tid < 5) {
            float s = 0.f;
            #pragma unroll
            for (int c = 0; c < 10; ++c) s += qfin[c] * fc_w[tid*10 + c];
            out[img*5 + tid] = s;
        }
    }

    // final cluster barrier: no CTA may exit while a neighbor's remote
    // ld.shared::cluster into this CTA's SMEM could still be in flight
    CLUSTER_ARRIVE();
    CLUSTER_WAIT();
}

extern "C" void kernel_launch(void* const* d_in, const int* in_sizes, int n_in,
                              void* d_out, int out_size) {
    const float* input_view = (const float*)d_in[0];
    const int*   coords     = (const int*)  d_in[1];
    const float* h_w        = (const float*)d_in[2];
    const float* h_b        = (const float*)d_in[3];
    const float* r_w        = (const float*)d_in[4];
    const float* q_w        = (const float*)d_in[5];
    const float* w          = (const float*)d_in[6];
    const float* fc_w       = (const float*)d_in[7];
    float* out = (float*)d_out;

    (void)in_sizes; (void)n_in; (void)out_size;

    vin_prep<<<1, 32>>>(h_w, h_b, r_w);

    cudaFuncSetAttribute(vin_main, cudaFuncAttributeMaxDynamicSharedMemorySize, SMEM_BYTES);
    vin_main<<<NIMG*NCTA, NTHR, SMEM_BYTES>>>(input_view, coords, q_w, w, fc_w, out);
}